// round 6
// baseline (speedup 1.0000x reference)
#include <cuda_runtime.h>
#include <cuda_fp16.h>

#define IN_SIZE  65536
#define OUT_SIZE 65536
#define NNZ      1048576
#define BATCH    32

// Scratch: transposed x as fp16 [IN, 32] and fp32 accumulator [OUT, 32].
__device__ __half g_xth[IN_SIZE * BATCH];   // 4 MB
__device__ float  g_ot[OUT_SIZE * BATCH];   // 8 MB

// ---------------------------------------------------------------------------
// prep: zero g_ot slice + transpose x [32, IN] -> g_xth [IN, 32] (fp16).
// Tile = 64 input-cols x 32 batch, stride-33 smem (conflict-free both phases).
// Block = 256 threads. Grid = 1024.
// ---------------------------------------------------------------------------
__global__ void prep_kernel(const float* __restrict__ x) {
    __shared__ float tile[64][33];
    const int t    = threadIdx.x;
    const int base = blockIdx.x * 64;    // input-feature offset

    // Zero this block's slice of g_ot: 2048 floats = 512 float4.
    float4* oz = reinterpret_cast<float4*>(g_ot) + blockIdx.x * 512;
    const float4 z = make_float4(0.f, 0.f, 0.f, 0.f);
    oz[t]       = z;
    oz[t + 256] = z;

    // Load: thread (b = t>>3, j0 = t&7) reads float4 along features;
    // scalar STS at bank (4*j0 + c + b) -- conflict-free per warp.
    const int b  = t >> 3;
    const int j0 = t & 7;
    #pragma unroll
    for (int i = 0; i < 2; i++) {
        const int j = j0 + 8 * i;
        const float4 v = *reinterpret_cast<const float4*>(
            &x[b * IN_SIZE + base + 4 * j]);
        tile[4 * j + 0][b] = v.x;
        tile[4 * j + 1][b] = v.y;
        tile[4 * j + 2][b] = v.z;
        tile[4 * j + 3][b] = v.w;
    }
    __syncthreads();

    // Store: convert to half, 4 halves (uint2) per thread per step.
    uint2* xt2 = reinterpret_cast<uint2*>(g_xth) + blockIdx.x * 512;
    #pragma unroll
    for (int i = 0; i < 2; i++) {
        const int g  = t + i * 256;      // uint2 index (4 halves)
        const int n  = g >> 3;
        const int b0 = (g * 4) & 31;
        __half2 h0 = __floats2half2_rn(tile[n][b0],     tile[n][b0 + 1]);
        __half2 h1 = __floats2half2_rn(tile[n][b0 + 2], tile[n][b0 + 3]);
        uint2 u;
        u.x = *reinterpret_cast<unsigned*>(&h0);
        u.y = *reinterpret_cast<unsigned*>(&h1);
        xt2[g] = u;
    }
}

// ---------------------------------------------------------------------------
// Scatter: warp handles 32 edges, 8 edges per iteration.
// Lane quartet q = lane>>2 owns edge j*8+q; its 4 lanes cover the 64B fp16
// batch row as 4 uint4s. Per lane: 1 LDG.128 + 8 h2f converts + 2 red.v4.
// ---------------------------------------------------------------------------
__global__ void scatter_kernel(const float* __restrict__ w,
                               const int* __restrict__ dst,
                               const int* __restrict__ src) {
    const int warpId = (blockIdx.x * blockDim.x + threadIdx.x) >> 5;
    const int lane   = threadIdx.x & 31;
    const int base   = warpId * 32;

    const float wv = __ldg(&w[base + lane]);
    const int   sv = __ldg(&src[base + lane]);
    const int   dv = __ldg(&dst[base + lane]);

    const int q = lane >> 2;   // edge slot within group of 8
    const int r = lane & 3;    // 16B chunk (8 halves) within the 64B row

    #pragma unroll
    for (int j = 0; j < 4; j++) {
        const int   e  = j * 8 + q;
        const float wj = __shfl_sync(0xffffffffu, wv, e);
        const int   sj = __shfl_sync(0xffffffffu, sv, e);
        const int   dj = __shfl_sync(0xffffffffu, dv, e);

        const uint4 hv = *reinterpret_cast<const uint4*>(&g_xth[sj * 32 + r * 8]);
        const float2 f0 = __half22float2(*reinterpret_cast<const __half2*>(&hv.x));
        const float2 f1 = __half22float2(*reinterpret_cast<const __half2*>(&hv.y));
        const float2 f2 = __half22float2(*reinterpret_cast<const __half2*>(&hv.z));
        const float2 f3 = __half22float2(*reinterpret_cast<const __half2*>(&hv.w));

        float* p = &g_ot[dj * 32 + r * 8];
        asm volatile("red.global.add.v4.f32 [%0], {%1, %2, %3, %4};"
                     :: "l"(p),
                        "f"(f0.x * wj), "f"(f0.y * wj),
                        "f"(f1.x * wj), "f"(f1.y * wj) : "memory");
        asm volatile("red.global.add.v4.f32 [%0], {%1, %2, %3, %4};"
                     :: "l"(p + 4),
                        "f"(f2.x * wj), "f"(f2.y * wj),
                        "f"(f3.x * wj), "f"(f3.y * wj) : "memory");
    }
}

// ---------------------------------------------------------------------------
// finish: transpose g_ot [OUT, 32] -> out [32, OUT].
// LDG.128 from g_ot, conflict-free smem, STG.128 to out. Grid = 1024.
// ---------------------------------------------------------------------------
__global__ void finish_kernel(float* __restrict__ out) {
    __shared__ float tile[64][33];
    const int t    = threadIdx.x;
    const int base = blockIdx.x * 64;    // output-feature offset

    const float4* ot4 = reinterpret_cast<const float4*>(g_ot) + blockIdx.x * 512;
    #pragma unroll
    for (int i = 0; i < 2; i++) {
        const int g  = t + i * 256;
        const float4 v = ot4[g];
        const int n  = g >> 3;
        const int b0 = (g * 4) & 31;
        tile[n][b0]     = v.x;
        tile[n][b0 + 1] = v.y;
        tile[n][b0 + 2] = v.z;
        tile[n][b0 + 3] = v.w;
    }
    __syncthreads();

    const int b  = t >> 3;
    const int j0 = t & 7;
    #pragma unroll
    for (int i = 0; i < 2; i++) {
        const int j = j0 + 8 * i;
        const float4 r = make_float4(tile[4 * j + 0][b], tile[4 * j + 1][b],
                                     tile[4 * j + 2][b], tile[4 * j + 3][b]);
        *reinterpret_cast<float4*>(&out[b * OUT_SIZE + base + 4 * j]) = r;
    }
}

extern "C" void kernel_launch(void* const* d_in, const int* in_sizes, int n_in,
                              void* d_out, int out_size) {
    const float* x       = (const float*)d_in[0];
    const float* weights = (const float*)d_in[1];
    const int*   dst_idx = (const int*)d_in[2];
    const int*   src_idx = (const int*)d_in[3];
    float*       out     = (float*)d_out;

    // 1) transpose x into fp16 [IN, 32] + zero accumulator (fused)
    prep_kernel<<<IN_SIZE / 64, 256>>>(x);

    // 2) scatter-accumulate: 1M edges, warp per 32 edges
    scatter_kernel<<<NNZ / 32 / 8, 256>>>(weights, dst_idx, src_idx);

    // 3) transpose accumulator into d_out [B, OUT]
    finish_kernel<<<OUT_SIZE / 64, 256>>>(out);
}

// round 7
// speedup vs baseline: 1.3478x; 1.3478x over previous
#include <cuda_runtime.h>
#include <cuda_fp16.h>

#define IN_SIZE  65536
#define OUT_SIZE 65536
#define NNZ      1048576
#define BATCH    32

// Scratch: transposed x as fp16 [IN, 32] and fp32 accumulator [OUT, 32].
__device__ __half g_xth[IN_SIZE * BATCH];   // 4 MB
__device__ float  g_ot[OUT_SIZE * BATCH];   // 8 MB

// ---------------------------------------------------------------------------
// prep: zero g_ot slice + transpose x [32, IN] -> g_xth [IN, 32] (fp16).
// Tile = 64 input-cols x 32 batch, stride-33 smem (conflict-free both phases).
// Block = 256 threads. Grid = 1024.
// ---------------------------------------------------------------------------
__global__ void prep_kernel(const float* __restrict__ x) {
    __shared__ float tile[64][33];
    const int t    = threadIdx.x;
    const int base = blockIdx.x * 64;    // input-feature offset

    // Zero this block's slice of g_ot: 2048 floats = 512 float4.
    float4* oz = reinterpret_cast<float4*>(g_ot) + blockIdx.x * 512;
    const float4 z = make_float4(0.f, 0.f, 0.f, 0.f);
    oz[t]       = z;
    oz[t + 256] = z;

    // Load: thread (b = t>>3, j0 = t&7) reads float4 along features;
    // scalar STS at bank (4*j0 + c + b) -- conflict-free per warp.
    const int b  = t >> 3;
    const int j0 = t & 7;
    #pragma unroll
    for (int i = 0; i < 2; i++) {
        const int j = j0 + 8 * i;
        const float4 v = *reinterpret_cast<const float4*>(
            &x[b * IN_SIZE + base + 4 * j]);
        tile[4 * j + 0][b] = v.x;
        tile[4 * j + 1][b] = v.y;
        tile[4 * j + 2][b] = v.z;
        tile[4 * j + 3][b] = v.w;
    }
    __syncthreads();

    // Store: convert to half, 4 halves (uint2) per thread per step.
    uint2* xt2 = reinterpret_cast<uint2*>(g_xth) + blockIdx.x * 512;
    #pragma unroll
    for (int i = 0; i < 2; i++) {
        const int g  = t + i * 256;      // uint2 index (4 halves)
        const int n  = g >> 3;
        const int b0 = (g * 4) & 31;
        __half2 h0 = __floats2half2_rn(tile[n][b0],     tile[n][b0 + 1]);
        __half2 h1 = __floats2half2_rn(tile[n][b0 + 2], tile[n][b0 + 3]);
        uint2 u;
        u.x = *reinterpret_cast<unsigned*>(&h0);
        u.y = *reinterpret_cast<unsigned*>(&h1);
        xt2[g] = u;
    }
}

// ---------------------------------------------------------------------------
// Scatter: warp handles 32 edges, 4 edges per iteration (octet mapping).
// Lane octet q = lane>>3 owns edge j*4+q; its 8 lanes cover the 64B fp16
// row as 8 uint2s and the 128B fp32 output row as 8 float4s. The RED
// instruction fully covers each output line in ONE wavefront (the round-6
// regression came from splitting it in two).
// ---------------------------------------------------------------------------
__global__ void scatter_kernel(const float* __restrict__ w,
                               const int* __restrict__ dst,
                               const int* __restrict__ src) {
    const int warpId = (blockIdx.x * blockDim.x + threadIdx.x) >> 5;
    const int lane   = threadIdx.x & 31;
    const int base   = warpId * 32;

    const float wv = __ldg(&w[base + lane]);
    const int   sv = __ldg(&src[base + lane]);
    const int   dv = __ldg(&dst[base + lane]);

    const int q = lane >> 3;   // edge slot within group of 4
    const int r = lane & 7;    // 8B chunk (4 halves / 4 floats) within row

    #pragma unroll
    for (int j = 0; j < 8; j++) {
        const int   e  = j * 4 + q;
        const float wj = __shfl_sync(0xffffffffu, wv, e);
        const int   sj = __shfl_sync(0xffffffffu, sv, e);
        const int   dj = __shfl_sync(0xffffffffu, dv, e);

        // 8B fp16 gather: 4 halves per lane, 64B per edge.
        const uint2 hv = *reinterpret_cast<const uint2*>(&g_xth[sj * 32 + r * 4]);
        const float2 f01 = __half22float2(*reinterpret_cast<const __half2*>(&hv.x));
        const float2 f23 = __half22float2(*reinterpret_cast<const __half2*>(&hv.y));

        // 16B fp32 RED per lane: octet covers the full 128B row contiguously.
        float* p = &g_ot[dj * 32 + r * 4];
        asm volatile("red.global.add.v4.f32 [%0], {%1, %2, %3, %4};"
                     :: "l"(p),
                        "f"(f01.x * wj), "f"(f01.y * wj),
                        "f"(f23.x * wj), "f"(f23.y * wj) : "memory");
    }
}

// ---------------------------------------------------------------------------
// finish: transpose g_ot [OUT, 32] -> out [32, OUT].
// LDG.128 from g_ot, conflict-free smem, STG.128 to out. Grid = 1024.
// ---------------------------------------------------------------------------
__global__ void finish_kernel(float* __restrict__ out) {
    __shared__ float tile[64][33];
    const int t    = threadIdx.x;
    const int base = blockIdx.x * 64;    // output-feature offset

    const float4* ot4 = reinterpret_cast<const float4*>(g_ot) + blockIdx.x * 512;
    #pragma unroll
    for (int i = 0; i < 2; i++) {
        const int g  = t + i * 256;
        const float4 v = ot4[g];
        const int n  = g >> 3;
        const int b0 = (g * 4) & 31;
        tile[n][b0]     = v.x;
        tile[n][b0 + 1] = v.y;
        tile[n][b0 + 2] = v.z;
        tile[n][b0 + 3] = v.w;
    }
    __syncthreads();

    const int b  = t >> 3;
    const int j0 = t & 7;
    #pragma unroll
    for (int i = 0; i < 2; i++) {
        const int j = j0 + 8 * i;
        const float4 r = make_float4(tile[4 * j + 0][b], tile[4 * j + 1][b],
                                     tile[4 * j + 2][b], tile[4 * j + 3][b]);
        *reinterpret_cast<float4*>(&out[b * OUT_SIZE + base + 4 * j]) = r;
    }
}

extern "C" void kernel_launch(void* const* d_in, const int* in_sizes, int n_in,
                              void* d_out, int out_size) {
    const float* x       = (const float*)d_in[0];
    const float* weights = (const float*)d_in[1];
    const int*   dst_idx = (const int*)d_in[2];
    const int*   src_idx = (const int*)d_in[3];
    float*       out     = (float*)d_out;

    // 1) transpose x into fp16 [IN, 32] + zero accumulator (fused)
    prep_kernel<<<IN_SIZE / 64, 256>>>(x);

    // 2) scatter-accumulate: 1M edges, warp per 32 edges
    scatter_kernel<<<NNZ / 32 / 8, 256>>>(weights, dst_idx, src_idx);

    // 3) transpose accumulator into d_out [B, OUT]
    finish_kernel<<<OUT_SIZE / 64, 256>>>(out);
}